// round 15
// baseline (speedup 1.0000x reference)
#include <cuda_runtime.h>
#include <cuda_fp16.h>
#include <cstdint>

#define BATCH 16
#define CIN   256
#define DMODEL 256
#define HEADS 8
#define NPH   32
#define HDIM  56
#define LTOT  3136
#define KWIN  9

// ---------------- device scratch ----------------
__device__ float g_wq[BATCH * CIN * HEADS];      // transposed: [b][c][h]
__device__ float g_s[BATCH * HEADS * LTOT];
__device__ __align__(16) __half g_v[BATCH * DMODEL * LTOT];
__device__ __align__(16) __half g_xhi[BATCH * CIN * LTOT];
__device__ __align__(16) __half g_ohi[BATCH * DMODEL * LTOT];
__device__ __align__(16) __half g_wvhi[DMODEL * CIN];
__device__ __align__(16) __half g_wphi[DMODEL * DMODEL];

// ---------------- PTX helpers ----------------
__device__ __forceinline__ uint32_t smem_u32(const void* p) {
    uint32_t a;
    asm("{ .reg .u64 t; cvta.to.shared.u64 t, %1; cvt.u32.u64 %0, t; }" : "=r"(a) : "l"(p));
    return a;
}
__device__ __forceinline__ void ldmA4(uint32_t* r, uint32_t addr) {
    asm volatile("ldmatrix.sync.aligned.m8n8.x4.shared.b16 {%0,%1,%2,%3}, [%4];"
                 : "=r"(r[0]), "=r"(r[1]), "=r"(r[2]), "=r"(r[3]) : "r"(addr));
}
__device__ __forceinline__ void ldmBt4(uint32_t* r, uint32_t addr) {
    asm volatile("ldmatrix.sync.aligned.m8n8.x4.trans.shared.b16 {%0,%1,%2,%3}, [%4];"
                 : "=r"(r[0]), "=r"(r[1]), "=r"(r[2]), "=r"(r[3]) : "r"(addr));
}
__device__ __forceinline__ void hmma(float* d, const uint32_t* a, const uint32_t* b) {
    asm volatile("mma.sync.aligned.m16n8k16.row.col.f32.f16.f16.f32 "
                 "{%0,%1,%2,%3}, {%4,%5,%6,%7}, {%8,%9}, {%0,%1,%2,%3};"
                 : "+f"(d[0]), "+f"(d[1]), "+f"(d[2]), "+f"(d[3])
                 : "r"(a[0]), "r"(a[1]), "r"(a[2]), "r"(a[3]), "r"(b[0]), "r"(b[1]));
}
__device__ __forceinline__ void cp16(uint32_t dst, const void* src) {
    asm volatile("cp.async.cg.shared.global [%0], [%1], 16;" :: "r"(dst), "l"(src));
}
#define CP_COMMIT() asm volatile("cp.async.commit_group;" ::: "memory")
__device__ __forceinline__ uint32_t sw128(uint32_t b) { return b ^ ((b >> 3) & 0x70); }

// ---------------- K0: fp16 cast of both weight matrices in one launch ----------------
__global__ void cast_weights_kernel(const float* __restrict__ wv,
                                    const float* __restrict__ wp,
                                    __half* __restrict__ wvh, __half* __restrict__ wph,
                                    int n4) {
    int i = blockIdx.x * 256 + threadIdx.x;
    const float* src;
    __half* dst;
    int j;
    if (i < n4) { src = wv; dst = wvh; j = i; }
    else if (i < 2 * n4) { src = wp; dst = wph; j = i - n4; }
    else return;
    float4 v = reinterpret_cast<const float4*>(src)[j];
    __half2* H = reinterpret_cast<__half2*>(dst);
    H[2 * j]     = __float22half2_rn(make_float2(v.x, v.y));
    H[2 * j + 1] = __float22half2_rn(make_float2(v.z, v.w));
}

// ---------------- K1: wq_t[b,c,h] = sum_n q[b,h*32+n] * Wk[h*32+n, c] ----------------
__global__ void wq_kernel(const float* __restrict__ q, const float* __restrict__ Wk) {
    int b = blockIdx.x;
    __shared__ float qs[DMODEL];
    if (threadIdx.x < DMODEL) qs[threadIdx.x] = q[b * DMODEL + threadIdx.x];
    __syncthreads();
    int c = threadIdx.x;
    float acc[HEADS] = {};
#pragma unroll
    for (int h = 0; h < HEADS; h++)
#pragma unroll 8
        for (int n = 0; n < NPH; n++)
            acc[h] += qs[h * NPH + n] * Wk[(h * NPH + n) * CIN + c];
#pragma unroll
    for (int h = 0; h < HEADS; h++)
        g_wq[(b * CIN + c) * HEADS + h] = acc[h];
}

// ---------------- K2: s + x fp16 cast fused (wq transposed, LDS.128 broadcast) ----------------
__global__ void __launch_bounds__(256) s_split_kernel(const float* __restrict__ x) {
    __shared__ float wq_s[CIN * HEADS];
    __shared__ float red[8][HEADS][64];
    const int b = blockIdx.y;
    {
        const float4* src = reinterpret_cast<const float4*>(g_wq + b * CIN * HEADS);
        float4* dst = reinterpret_cast<float4*>(wq_s);
        for (int i = threadIdx.x; i < CIN * HEADS / 4; i += 256) dst[i] = src[i];
    }
    __syncthreads();

    const int lp = threadIdx.x & 31;
    const int cs = threadIdx.x >> 5;
    const int l = blockIdx.x * 64 + lp * 2;
    const float* xb = x + (size_t)b * CIN * LTOT;
    __half* xhi = g_xhi + (size_t)b * CIN * LTOT;

    float acc[HEADS][2] = {};
#pragma unroll 8
    for (int cc = 0; cc < 32; cc++) {
        int c = cs * 32 + cc;
        size_t idx = (size_t)c * LTOT + l;
        float2 v = *reinterpret_cast<const float2*>(xb + idx);
        *reinterpret_cast<__half2*>(xhi + idx) = __float22half2_rn(v);
        float4 w0 = *reinterpret_cast<const float4*>(&wq_s[c * HEADS]);
        float4 w1 = *reinterpret_cast<const float4*>(&wq_s[c * HEADS + 4]);
        acc[0][0] += w0.x * v.x; acc[0][1] += w0.x * v.y;
        acc[1][0] += w0.y * v.x; acc[1][1] += w0.y * v.y;
        acc[2][0] += w0.z * v.x; acc[2][1] += w0.z * v.y;
        acc[3][0] += w0.w * v.x; acc[3][1] += w0.w * v.y;
        acc[4][0] += w1.x * v.x; acc[4][1] += w1.x * v.y;
        acc[5][0] += w1.y * v.x; acc[5][1] += w1.y * v.y;
        acc[6][0] += w1.z * v.x; acc[6][1] += w1.z * v.y;
        acc[7][0] += w1.w * v.x; acc[7][1] += w1.w * v.y;
    }
#pragma unroll
    for (int hh = 0; hh < HEADS; hh++) {
        red[cs][hh][lp * 2]     = acc[hh][0];
        red[cs][hh][lp * 2 + 1] = acc[hh][1];
    }
    __syncthreads();
    for (int i = threadIdx.x; i < HEADS * 64; i += 256) {
        int hh = i >> 6, l2i = i & 63;
        float s = 0.f;
#pragma unroll
        for (int c8 = 0; c8 < 8; c8++) s += red[c8][hh][l2i];
        g_s[(size_t)(b * HEADS + hh) * LTOT + blockIdx.x * 64 + l2i] = s;
    }
}

// ---------------- K3: HMMA GEMM, M=256 CTA tile, warp 64x32, 2 CTAs/SM ----------------
// stage (40KB): A 32K | X 8K; two stages = 80 KB.
#define STG 40960u
template <typename OutT>
__global__ void __launch_bounds__(256, 2) hgemm(
    const __half* __restrict__ Ahi, const __half* __restrict__ Xhi,
    OutT* __restrict__ C) {
    extern __shared__ __align__(1024) unsigned char sb[];
    const uint32_t s0 = smem_u32(sb);

    const int tid = threadIdx.x;
    const int wid = tid >> 5, lane = tid & 31;
    const int l0 = blockIdx.x * 64;
    const int b  = blockIdx.y;

    const int m_base = (wid >> 1) * 64;      // warp tile 64M x 32N
    const int n_base = (wid & 1) * 32;

    const __half* Xhi_b = Xhi + (size_t)b * CIN * LTOT;

    float acc[4][4][4];
#pragma unroll
    for (int mt = 0; mt < 4; mt++)
#pragma unroll
        for (int nt = 0; nt < 4; nt++)
#pragma unroll
            for (int i = 0; i < 4; i++) acc[mt][nt][i] = 0.f;

    auto load_chunk = [&](int c) {
        const int st = c & 1;
        const int k0 = c * 64;
        uint32_t dA = s0 + st * STG;
        uint32_t dX = dA + 32768;
#pragma unroll
        for (int j = 0; j < 8; j++) {        // A: 256 rows x 128B
            int idx = tid + j * 256;
            int row = idx >> 3, ch = idx & 7;
            uint32_t off = sw128(row * 128 + ch * 16);
            cp16(dA + off, Ahi + (size_t)row * CIN + k0 + ch * 8);
        }
#pragma unroll
        for (int j = 0; j < 2; j++) {        // X: 64 rows x 128B
            int idx = tid + j * 256;
            int row = idx >> 3, ch = idx & 7;
            uint32_t off = sw128(row * 128 + ch * 16);
            cp16(dX + off, Xhi_b + (size_t)(k0 + row) * LTOT + l0 + ch * 8);
        }
        CP_COMMIT();
    };

    load_chunk(0);
    const int b3 = lane >> 3, r8 = lane & 7;

    for (int c = 0; c < 4; c++) {
        asm volatile("cp.async.wait_group 0;" ::: "memory");
        __syncthreads();
        if (c + 1 < 4) load_chunk(c + 1);    // overlaps mma(c)

        const int st = c & 1;
        const uint32_t sA = s0 + st * STG;
        const uint32_t sX = sA + 32768;

#pragma unroll
        for (int kk = 0; kk < 4; kk++) {
            uint32_t bhi[2][4];
#pragma unroll
            for (int g = 0; g < 2; g++) {
                int krow = kk * 16 + (lane & 15);
                int ncol = n_base + g * 16 + ((lane >> 4) << 3);
                uint32_t byte = sw128((uint32_t)(krow * 128 + ncol * 2));
                ldmBt4(bhi[g], sX + byte);
            }
#pragma unroll
            for (int mt = 0; mt < 4; mt++) {
                uint32_t ahi[4];
                int row = m_base + mt * 16 + ((b3 & 1) << 3) + r8;
                uint32_t byte = sw128((uint32_t)(row * 128 + kk * 32 + ((b3 >> 1) << 4)));
                ldmA4(ahi, sA + byte);
#pragma unroll
                for (int g = 0; g < 2; g++)
#pragma unroll
                    for (int h = 0; h < 2; h++)
                        hmma(acc[mt][g * 2 + h], ahi, &bhi[g][h * 2]);
            }
        }
    }

    const int g = lane >> 2, j2 = (lane & 3) * 2;
    OutT* Cb = C + (size_t)b * DMODEL * LTOT;
#pragma unroll
    for (int mt = 0; mt < 4; mt++) {
        int mrow = m_base + mt * 16 + g;
#pragma unroll
        for (int nt = 0; nt < 4; nt++) {
            int col = l0 + n_base + nt * 8 + j2;
            if constexpr (sizeof(OutT) == 4) {
                *reinterpret_cast<float2*>(Cb + (size_t)mrow * LTOT + col) =
                    make_float2(acc[mt][nt][0], acc[mt][nt][1]);
                *reinterpret_cast<float2*>(Cb + (size_t)(mrow + 8) * LTOT + col) =
                    make_float2(acc[mt][nt][2], acc[mt][nt][3]);
            } else {
                *reinterpret_cast<__half2*>(Cb + (size_t)mrow * LTOT + col) =
                    __float22half2_rn(make_float2(acc[mt][nt][0], acc[mt][nt][1]));
                *reinterpret_cast<__half2*>(Cb + (size_t)(mrow + 8) * LTOT + col) =
                    __float22half2_rn(make_float2(acc[mt][nt][2], acc[mt][nt][3]));
            }
        }
    }
}

// ---------------- K4: fused softmax + AV gather with smem-staged v ----------------
__global__ void __launch_bounds__(256) attn_av_kernel(
    const float* __restrict__ pos_emb, const float* __restrict__ Wlin) {
    __shared__ float sm_at[KWIN][64];
    __shared__ __align__(4) __half sv[32][4 * 56];
    const int bh = blockIdx.y;
    const int b = bh >> 3, h = bh & 7;
    const int l0 = blockIdx.x * 64;
    const int tid = threadIdx.x;
    const int y0 = l0 / HDIM;

    {
        const __half* vbase = g_v + (size_t)(b * DMODEL + h * NPH) * LTOT;
#pragma unroll
        for (int t = 0; t < 14; t++) {
            int idx = tid + t * 256;
            int ch = idx / 112;
            int rem = idx - ch * 112;
            int r = rem / 28;
            int p2 = rem - r * 28;
            int gy = y0 - 1 + r;
            __half2 val = __float22half2_rn(make_float2(0.f, 0.f));
            if (gy >= 0 && gy < HDIM)
                val = *reinterpret_cast<const __half2*>(
                    vbase + (size_t)ch * LTOT + gy * HDIM + p2 * 2);
            *reinterpret_cast<__half2*>(&sv[ch][r * 56 + p2 * 2]) = val;
        }
    }

    if (tid < 64) {
        float scale = Wlin[0] + Wlin[1] + Wlin[2] + Wlin[3];
        int l = l0 + tid;
        int y = l / HDIM, xx = l % HDIM;
        const float* sp = g_s + (size_t)bh * LTOT;
        float logit[KWIN];
#pragma unroll
        for (int kh = 0; kh < 3; kh++)
#pragma unroll
            for (int kw = 0; kw < 3; kw++) {
                int yy = y + kh - 1, xz = xx + kw - 1;
                float svl = (yy >= 0 && yy < HDIM && xz >= 0 && xz < HDIM)
                                ? sp[yy * HDIM + xz] : 0.f;
                logit[kh * 3 + kw] = svl + pos_emb[kh + kw];
            }
        float m = logit[0];
#pragma unroll
        for (int k = 1; k < KWIN; k++) m = fmaxf(m, logit[k]);
        float e[KWIN], sum = 0.f;
#pragma unroll
        for (int k = 0; k < KWIN; k++) { e[k] = __expf(logit[k] - m); sum += e[k]; }
        float inv = scale / sum;
#pragma unroll
        for (int k = 0; k < KWIN; k++) sm_at[k][tid] = e[k] * inv;
    }
    __syncthreads();

    const int lp = tid & 31;
    const int dg = tid >> 5;
    float att[2][KWIN];
    int off[2][KWIN];
#pragma unroll
    for (int e = 0; e < 2; e++) {
        int ll = lp * 2 + e;
        int l = l0 + ll;
        int y = l / HDIM, xx = l % HDIM;
#pragma unroll
        for (int kh = 0; kh < 3; kh++)
#pragma unroll
            for (int kw = 0; kw < 3; kw++) {
                int k = kh * 3 + kw;
                int yy = y + kh - 1, xz = xx + kw - 1;
                bool ok = (yy >= 0 && yy < HDIM && xz >= 0 && xz < HDIM);
                att[e][k] = ok ? sm_at[k][ll] : 0.f;
                off[e][k] = ok ? (yy - (y0 - 1)) * 56 + xz : 0;
            }
    }
    const size_t obase = (size_t)(b * DMODEL + h * NPH + dg * 4) * LTOT;
#pragma unroll
    for (int dd = 0; dd < 4; dd++) {
        const __half* vp = &sv[dg * 4 + dd][0];
        float o[2];
#pragma unroll
        for (int e = 0; e < 2; e++) {
            float a = 0.f;
#pragma unroll
            for (int k = 0; k < KWIN; k++)
                a += att[e][k] * __half2float(vp[off[e][k]]);
            o[e] = a;
        }
        size_t oidx = obase + (size_t)dd * LTOT + l0 + lp * 2;
        *reinterpret_cast<__half2*>(g_ohi + oidx) =
            __float22half2_rn(make_float2(o[0], o[1]));
    }
}

// ---------------- host launcher ----------------
extern "C" void kernel_launch(void* const* d_in, const int* in_sizes, int n_in,
                              void* d_out, int out_size) {
    const float* x       = (const float*)d_in[0];
    const float* q       = (const float*)d_in[1];
    const float* Wk      = (const float*)d_in[2];
    const float* Wv      = (const float*)d_in[3];
    const float* pos_emb = (const float*)d_in[4];
    const float* Wlin    = (const float*)d_in[5];
    const float* Wproj   = (const float*)d_in[6];
    float* out = (float*)d_out;

    void *pv, *pxhi, *pohi, *pwvhi, *pwphi;
    cudaGetSymbolAddress(&pv, g_v);
    cudaGetSymbolAddress(&pxhi, g_xhi);
    cudaGetSymbolAddress(&pohi, g_ohi);
    cudaGetSymbolAddress(&pwvhi, g_wvhi);
    cudaGetSymbolAddress(&pwphi, g_wphi);

    static bool attr_set = false;
    if (!attr_set) {
        cudaFuncSetAttribute(hgemm<__half>,
                             cudaFuncAttributeMaxDynamicSharedMemorySize, 2 * STG);
        cudaFuncSetAttribute(hgemm<float>,
                             cudaFuncAttributeMaxDynamicSharedMemorySize, 2 * STG);
        attr_set = true;
    }

    const int WN4 = DMODEL * CIN / 4;

    wq_kernel<<<BATCH, 256>>>(q, Wk);
    cast_weights_kernel<<<(2 * WN4 + 255) / 256, 256>>>(
        Wv, Wproj, (__half*)pwvhi, (__half*)pwphi, WN4);
    s_split_kernel<<<dim3(LTOT / 64, BATCH), 256>>>(x);

    hgemm<__half><<<dim3(LTOT / 64, BATCH), 256, 2 * STG>>>(
        (const __half*)pwvhi, (const __half*)pxhi, (__half*)pv);

    attn_av_kernel<<<dim3(LTOT / 64, BATCH * HEADS), 256>>>(pos_emb, Wlin);

    hgemm<float><<<dim3(LTOT / 64, BATCH), 256, 2 * STG>>>(
        (const __half*)pwphi, (const __half*)pohi, out);
}

// round 16
// speedup vs baseline: 1.1694x; 1.1694x over previous
#include <cuda_runtime.h>
#include <cuda_fp16.h>
#include <cstdint>

#define BATCH 16
#define CIN   256
#define DMODEL 256
#define HEADS 8
#define NPH   32
#define HDIM  56
#define LTOT  3136
#define KWIN  9

// ---------------- device scratch ----------------
__device__ float g_wq[BATCH * CIN * HEADS];      // transposed: [b][c][h]
__device__ float g_s[BATCH * HEADS * LTOT];
__device__ __align__(16) __half g_v[BATCH * DMODEL * LTOT];
__device__ __align__(16) __half g_xhi[BATCH * CIN * LTOT];
__device__ __align__(16) __half g_ohi[BATCH * DMODEL * LTOT];
__device__ __align__(16) __half g_wvhi[DMODEL * CIN];
__device__ __align__(16) __half g_wphi[DMODEL * DMODEL];

// ---------------- PTX helpers ----------------
__device__ __forceinline__ uint32_t smem_u32(const void* p) {
    uint32_t a;
    asm("{ .reg .u64 t; cvta.to.shared.u64 t, %1; cvt.u32.u64 %0, t; }" : "=r"(a) : "l"(p));
    return a;
}
__device__ __forceinline__ void ldmA4(uint32_t* r, uint32_t addr) {
    asm volatile("ldmatrix.sync.aligned.m8n8.x4.shared.b16 {%0,%1,%2,%3}, [%4];"
                 : "=r"(r[0]), "=r"(r[1]), "=r"(r[2]), "=r"(r[3]) : "r"(addr));
}
__device__ __forceinline__ void ldmBt4(uint32_t* r, uint32_t addr) {
    asm volatile("ldmatrix.sync.aligned.m8n8.x4.trans.shared.b16 {%0,%1,%2,%3}, [%4];"
                 : "=r"(r[0]), "=r"(r[1]), "=r"(r[2]), "=r"(r[3]) : "r"(addr));
}
__device__ __forceinline__ void hmma(float* d, const uint32_t* a, const uint32_t* b) {
    asm volatile("mma.sync.aligned.m16n8k16.row.col.f32.f16.f16.f32 "
                 "{%0,%1,%2,%3}, {%4,%5,%6,%7}, {%8,%9}, {%0,%1,%2,%3};"
                 : "+f"(d[0]), "+f"(d[1]), "+f"(d[2]), "+f"(d[3])
                 : "r"(a[0]), "r"(a[1]), "r"(a[2]), "r"(a[3]), "r"(b[0]), "r"(b[1]));
}
__device__ __forceinline__ void cp16(uint32_t dst, const void* src) {
    asm volatile("cp.async.cg.shared.global [%0], [%1], 16;" :: "r"(dst), "l"(src));
}
#define CP_COMMIT() asm volatile("cp.async.commit_group;" ::: "memory")
__device__ __forceinline__ uint32_t sw128(uint32_t b) { return b ^ ((b >> 3) & 0x70); }

// ---------------- K0: fp16 cast of both weight matrices in one launch ----------------
__global__ void cast_weights_kernel(const float* __restrict__ wv,
                                    const float* __restrict__ wp,
                                    __half* __restrict__ wvh, __half* __restrict__ wph,
                                    int n4) {
    int i = blockIdx.x * 256 + threadIdx.x;
    const float* src;
    __half* dst;
    int j;
    if (i < n4) { src = wv; dst = wvh; j = i; }
    else if (i < 2 * n4) { src = wp; dst = wph; j = i - n4; }
    else return;
    float4 v = reinterpret_cast<const float4*>(src)[j];
    __half2* H = reinterpret_cast<__half2*>(dst);
    H[2 * j]     = __float22half2_rn(make_float2(v.x, v.y));
    H[2 * j + 1] = __float22half2_rn(make_float2(v.z, v.w));
}

// ---------------- K1: wq_t[b,c,h] — grid (B*H), block 256 (one c each) ----------------
__global__ void wq_kernel(const float* __restrict__ q, const float* __restrict__ Wk) {
    int bh = blockIdx.x;
    int b = bh >> 3, h = bh & 7;
    __shared__ float qs[NPH];
    if (threadIdx.x < NPH) qs[threadIdx.x] = q[b * DMODEL + h * NPH + threadIdx.x];
    __syncthreads();
    int c = threadIdx.x;
    float acc = 0.f;
#pragma unroll 8
    for (int n = 0; n < NPH; n++)
        acc += qs[n] * Wk[(h * NPH + n) * CIN + c];
    g_wq[(b * CIN + c) * HEADS + h] = acc;
}

// ---------------- K2: s + x fp16 cast fused (wq transposed, LDS.128 broadcast) ----------------
__global__ void __launch_bounds__(256) s_split_kernel(const float* __restrict__ x) {
    __shared__ float wq_s[CIN * HEADS];
    __shared__ float red[8][HEADS][64];
    const int b = blockIdx.y;
    {
        const float4* src = reinterpret_cast<const float4*>(g_wq + b * CIN * HEADS);
        float4* dst = reinterpret_cast<float4*>(wq_s);
        for (int i = threadIdx.x; i < CIN * HEADS / 4; i += 256) dst[i] = src[i];
    }
    __syncthreads();

    const int lp = threadIdx.x & 31;
    const int cs = threadIdx.x >> 5;
    const int l = blockIdx.x * 64 + lp * 2;
    const float* xb = x + (size_t)b * CIN * LTOT;
    __half* xhi = g_xhi + (size_t)b * CIN * LTOT;

    float acc[HEADS][2] = {};
#pragma unroll 8
    for (int cc = 0; cc < 32; cc++) {
        int c = cs * 32 + cc;
        size_t idx = (size_t)c * LTOT + l;
        float2 v = *reinterpret_cast<const float2*>(xb + idx);
        *reinterpret_cast<__half2*>(xhi + idx) = __float22half2_rn(v);
        float4 w0 = *reinterpret_cast<const float4*>(&wq_s[c * HEADS]);
        float4 w1 = *reinterpret_cast<const float4*>(&wq_s[c * HEADS + 4]);
        acc[0][0] += w0.x * v.x; acc[0][1] += w0.x * v.y;
        acc[1][0] += w0.y * v.x; acc[1][1] += w0.y * v.y;
        acc[2][0] += w0.z * v.x; acc[2][1] += w0.z * v.y;
        acc[3][0] += w0.w * v.x; acc[3][1] += w0.w * v.y;
        acc[4][0] += w1.x * v.x; acc[4][1] += w1.x * v.y;
        acc[5][0] += w1.y * v.x; acc[5][1] += w1.y * v.y;
        acc[6][0] += w1.z * v.x; acc[6][1] += w1.z * v.y;
        acc[7][0] += w1.w * v.x; acc[7][1] += w1.w * v.y;
    }
#pragma unroll
    for (int hh = 0; hh < HEADS; hh++) {
        red[cs][hh][lp * 2]     = acc[hh][0];
        red[cs][hh][lp * 2 + 1] = acc[hh][1];
    }
    __syncthreads();
    for (int i = threadIdx.x; i < HEADS * 64; i += 256) {
        int hh = i >> 6, l2i = i & 63;
        float s = 0.f;
#pragma unroll
        for (int c8 = 0; c8 < 8; c8++) s += red[c8][hh][l2i];
        g_s[(size_t)(b * HEADS + hh) * LTOT + blockIdx.x * 64 + l2i] = s;
    }
}

// ---------------- K3: HMMA GEMM, M=128 tile, 4 buffers, all-upfront prefetch ----------------
// stage (24KB): A 16K | X 8K; four stages = 96 KB; 2 CTAs/SM.
#define STG 24576u
template <typename OutT>
__global__ void __launch_bounds__(256, 2) hgemm(
    const __half* __restrict__ Ahi, const __half* __restrict__ Xhi,
    OutT* __restrict__ C) {
    extern __shared__ __align__(1024) unsigned char sb[];
    const uint32_t s0 = smem_u32(sb);

    const int tid = threadIdx.x;
    const int wid = tid >> 5, lane = tid & 31;
    const int l0 = blockIdx.x * 64;
    const int m0 = blockIdx.y * 128;
    const int b  = blockIdx.z;

    const int m_base = (wid >> 1) * 32;
    const int n_base = (wid & 1) * 32;

    const __half* Xhi_b = Xhi + (size_t)b * CIN * LTOT;

    float acc[2][4][4];
#pragma unroll
    for (int mt = 0; mt < 2; mt++)
#pragma unroll
        for (int nt = 0; nt < 4; nt++)
#pragma unroll
            for (int i = 0; i < 4; i++) acc[mt][nt][i] = 0.f;

    auto load_chunk = [&](int c) {
        const int k0 = c * 64;
        uint32_t dA = s0 + (uint32_t)c * STG;
        uint32_t dX = dA + 16384;
#pragma unroll
        for (int j = 0; j < 4; j++) {
            int idx = tid + j * 256;
            int row = idx >> 3, ch = idx & 7;
            uint32_t off = sw128(row * 128 + ch * 16);
            cp16(dA + off, Ahi + (size_t)(m0 + row) * CIN + k0 + ch * 8);
        }
#pragma unroll
        for (int j = 0; j < 2; j++) {
            int idx = tid + j * 256;
            int row = idx >> 3, ch = idx & 7;
            uint32_t off = sw128(row * 128 + ch * 16);
            cp16(dX + off, Xhi_b + (size_t)(k0 + row) * LTOT + l0 + ch * 8);
        }
        CP_COMMIT();
    };

    // issue ALL chunk loads up front — max MLP, no buffer reuse
    load_chunk(0);
    load_chunk(1);
    load_chunk(2);
    load_chunk(3);

    const int b3 = lane >> 3, r8 = lane & 7;

#pragma unroll
    for (int c = 0; c < 4; c++) {
        if (c == 0)      asm volatile("cp.async.wait_group 3;" ::: "memory");
        else if (c == 1) asm volatile("cp.async.wait_group 2;" ::: "memory");
        else if (c == 2) asm volatile("cp.async.wait_group 1;" ::: "memory");
        else             asm volatile("cp.async.wait_group 0;" ::: "memory");
        __syncthreads();    // cross-warp visibility of chunk c

        const uint32_t sA = s0 + (uint32_t)c * STG;
        const uint32_t sX = sA + 16384;

#pragma unroll
        for (int kk = 0; kk < 4; kk++) {
            uint32_t ahi[2][4], bhi[2][4];
#pragma unroll
            for (int mt = 0; mt < 2; mt++) {
                int row = m_base + mt * 16 + ((b3 & 1) << 3) + r8;
                uint32_t byte = sw128((uint32_t)(row * 128 + kk * 32 + ((b3 >> 1) << 4)));
                ldmA4(ahi[mt], sA + byte);
            }
#pragma unroll
            for (int g = 0; g < 2; g++) {
                int krow = kk * 16 + (lane & 15);
                int ncol = n_base + g * 16 + ((lane >> 4) << 3);
                uint32_t byte = sw128((uint32_t)(krow * 128 + ncol * 2));
                ldmBt4(bhi[g], sX + byte);
            }
#pragma unroll
            for (int mt = 0; mt < 2; mt++)
#pragma unroll
                for (int g = 0; g < 2; g++)
#pragma unroll
                    for (int h = 0; h < 2; h++)
                        hmma(acc[mt][g * 2 + h], ahi[mt], &bhi[g][h * 2]);
        }
    }

    const int g = lane >> 2, j2 = (lane & 3) * 2;
    OutT* Cb = C + (size_t)b * DMODEL * LTOT;
#pragma unroll
    for (int mt = 0; mt < 2; mt++) {
        int mrow = m0 + m_base + mt * 16 + g;
#pragma unroll
        for (int nt = 0; nt < 4; nt++) {
            int col = l0 + n_base + nt * 8 + j2;
            if constexpr (sizeof(OutT) == 4) {
                *reinterpret_cast<float2*>(Cb + (size_t)mrow * LTOT + col) =
                    make_float2(acc[mt][nt][0], acc[mt][nt][1]);
                *reinterpret_cast<float2*>(Cb + (size_t)(mrow + 8) * LTOT + col) =
                    make_float2(acc[mt][nt][2], acc[mt][nt][3]);
            } else {
                *reinterpret_cast<__half2*>(Cb + (size_t)mrow * LTOT + col) =
                    __float22half2_rn(make_float2(acc[mt][nt][0], acc[mt][nt][1]));
                *reinterpret_cast<__half2*>(Cb + (size_t)(mrow + 8) * LTOT + col) =
                    __float22half2_rn(make_float2(acc[mt][nt][2], acc[mt][nt][3]));
            }
        }
    }
}

// ---------------- K4: fused softmax + AV gather with smem-staged v ----------------
__global__ void __launch_bounds__(256) attn_av_kernel(
    const float* __restrict__ pos_emb, const float* __restrict__ Wlin) {
    __shared__ float sm_at[KWIN][64];
    __shared__ __align__(4) __half sv[32][4 * 56];
    const int bh = blockIdx.y;
    const int b = bh >> 3, h = bh & 7;
    const int l0 = blockIdx.x * 64;
    const int tid = threadIdx.x;
    const int y0 = l0 / HDIM;

    {
        const __half* vbase = g_v + (size_t)(b * DMODEL + h * NPH) * LTOT;
#pragma unroll
        for (int t = 0; t < 14; t++) {
            int idx = tid + t * 256;
            int ch = idx / 112;
            int rem = idx - ch * 112;
            int r = rem / 28;
            int p2 = rem - r * 28;
            int gy = y0 - 1 + r;
            __half2 val = __float22half2_rn(make_float2(0.f, 0.f));
            if (gy >= 0 && gy < HDIM)
                val = *reinterpret_cast<const __half2*>(
                    vbase + (size_t)ch * LTOT + gy * HDIM + p2 * 2);
            *reinterpret_cast<__half2*>(&sv[ch][r * 56 + p2 * 2]) = val;
        }
    }

    if (tid < 64) {
        float scale = Wlin[0] + Wlin[1] + Wlin[2] + Wlin[3];
        int l = l0 + tid;
        int y = l / HDIM, xx = l % HDIM;
        const float* sp = g_s + (size_t)bh * LTOT;
        float logit[KWIN];
#pragma unroll
        for (int kh = 0; kh < 3; kh++)
#pragma unroll
            for (int kw = 0; kw < 3; kw++) {
                int yy = y + kh - 1, xz = xx + kw - 1;
                float svl = (yy >= 0 && yy < HDIM && xz >= 0 && xz < HDIM)
                                ? sp[yy * HDIM + xz] : 0.f;
                logit[kh * 3 + kw] = svl + pos_emb[kh + kw];
            }
        float m = logit[0];
#pragma unroll
        for (int k = 1; k < KWIN; k++) m = fmaxf(m, logit[k]);
        float e[KWIN], sum = 0.f;
#pragma unroll
        for (int k = 0; k < KWIN; k++) { e[k] = __expf(logit[k] - m); sum += e[k]; }
        float inv = scale / sum;
#pragma unroll
        for (int k = 0; k < KWIN; k++) sm_at[k][tid] = e[k] * inv;
    }
    __syncthreads();

    const int lp = tid & 31;
    const int dg = tid >> 5;
    float att[2][KWIN];
    int off[2][KWIN];
#pragma unroll
    for (int e = 0; e < 2; e++) {
        int ll = lp * 2 + e;
        int l = l0 + ll;
        int y = l / HDIM, xx = l % HDIM;
#pragma unroll
        for (int kh = 0; kh < 3; kh++)
#pragma unroll
            for (int kw = 0; kw < 3; kw++) {
                int k = kh * 3 + kw;
                int yy = y + kh - 1, xz = xx + kw - 1;
                bool ok = (yy >= 0 && yy < HDIM && xz >= 0 && xz < HDIM);
                att[e][k] = ok ? sm_at[k][ll] : 0.f;
                off[e][k] = ok ? (yy - (y0 - 1)) * 56 + xz : 0;
            }
    }
    const size_t obase = (size_t)(b * DMODEL + h * NPH + dg * 4) * LTOT;
#pragma unroll
    for (int dd = 0; dd < 4; dd++) {
        const __half* vp = &sv[dg * 4 + dd][0];
        float o[2];
#pragma unroll
        for (int e = 0; e < 2; e++) {
            float a = 0.f;
#pragma unroll
            for (int k = 0; k < KWIN; k++)
                a += att[e][k] * __half2float(vp[off[e][k]]);
            o[e] = a;
        }
        size_t oidx = obase + (size_t)dd * LTOT + l0 + lp * 2;
        *reinterpret_cast<__half2*>(g_ohi + oidx) =
            __float22half2_rn(make_float2(o[0], o[1]));
    }
}

// ---------------- host launcher ----------------
extern "C" void kernel_launch(void* const* d_in, const int* in_sizes, int n_in,
                              void* d_out, int out_size) {
    const float* x       = (const float*)d_in[0];
    const float* q       = (const float*)d_in[1];
    const float* Wk      = (const float*)d_in[2];
    const float* Wv      = (const float*)d_in[3];
    const float* pos_emb = (const float*)d_in[4];
    const float* Wlin    = (const float*)d_in[5];
    const float* Wproj   = (const float*)d_in[6];
    float* out = (float*)d_out;

    void *pv, *pxhi, *pohi, *pwvhi, *pwphi;
    cudaGetSymbolAddress(&pv, g_v);
    cudaGetSymbolAddress(&pxhi, g_xhi);
    cudaGetSymbolAddress(&pohi, g_ohi);
    cudaGetSymbolAddress(&pwvhi, g_wvhi);
    cudaGetSymbolAddress(&pwphi, g_wphi);

    static bool attr_set = false;
    if (!attr_set) {
        cudaFuncSetAttribute(hgemm<__half>,
                             cudaFuncAttributeMaxDynamicSharedMemorySize, 4 * STG);
        cudaFuncSetAttribute(hgemm<float>,
                             cudaFuncAttributeMaxDynamicSharedMemorySize, 4 * STG);
        attr_set = true;
    }

    const int WN4 = DMODEL * CIN / 4;

    wq_kernel<<<BATCH * HEADS, 256>>>(q, Wk);
    cast_weights_kernel<<<(2 * WN4 + 255) / 256, 256>>>(
        Wv, Wproj, (__half*)pwvhi, (__half*)pwphi, WN4);
    s_split_kernel<<<dim3(LTOT / 64, BATCH), 256>>>(x);

    hgemm<__half><<<dim3(LTOT / 64, DMODEL / 128, BATCH), 256, 4 * STG>>>(
        (const __half*)pwvhi, (const __half*)pxhi, (__half*)pv);

    attn_av_kernel<<<dim3(LTOT / 64, BATCH * HEADS), 256>>>(pos_emb, Wlin);

    hgemm<float><<<dim3(LTOT / 64, DMODEL / 128, BATCH), 256, 4 * STG>>>(
        (const __half*)pwphi, (const __half*)pohi, out);
}